// round 15
// baseline (speedup 1.0000x reference)
#include <cuda_runtime.h>
#include <cuda_bf16.h>
#include <math.h>

// Problem constants
#define NB    1024
#define NP    256
#define EPG   4096
#define ETOT  (NB*EPG)
#define FIN   7
#define HD    64
#define KC    50
#define SK    54          // EVEN stride -> 8B-aligned col pairs for LDS.64/f32x2

// dynamic smem layout (bytes)
//  0      : sE   u16[4096]            8192
//  8192   : sW   float[4096]          16384
//  24576  : sXA  float[4096]          16384   (x/h0; sort scratch; xp)
//  40960  : sA   float[16384]         65536   (Acnt u32 / t / AS[256*54]+Ap / t2)
//  106496 : sH   float[16384]         65536   (dst-sort scratch; h; h2a)
//  172032 : sS   float[256*54]        55296
//  227328 : sRed float[288]           1152
#define SMEM_BYTES 228480

__device__ float g_part[NB * 4];
__device__ unsigned int g_ctr = 0;

typedef unsigned long long ull;

// ---- packed f32x2 helpers (Blackwell FFMA2) ----
__device__ __forceinline__ ull pk2(float a, float b) {
    ull r;
    asm("mov.b64 %0, {%1,%2};" : "=l"(r) : "f"(a), "f"(b));
    return r;
}
__device__ __forceinline__ void upk2(ull v, float& a, float& b) {
    asm("mov.b64 {%0,%1}, %2;" : "=f"(a), "=f"(b) : "l"(v));
}
__device__ __forceinline__ void fma2(ull& d, ull a, ull b) {
    asm("fma.rn.f32x2 %0, %1, %2, %3;" : "=l"(d) : "l"(a), "l"(b), "l"(d));
}

__global__ __launch_bounds__(512, 1) void net_main(
    const float* __restrict__ x,
    const float* __restrict__ W1a, const float* __restrict__ b1a,
    const float* __restrict__ W1b, const float* __restrict__ b1b,
    const float* __restrict__ Wp,  const float* __restrict__ bp,
    const float* __restrict__ W2a, const float* __restrict__ b2a,
    const float* __restrict__ W2b, const float* __restrict__ b2b,
    const float* __restrict__ Wl,  const float* __restrict__ bl,
    const int* __restrict__ edge,   // [2][ETOT] int32
    float* __restrict__ out, int out_size)
{
    extern __shared__ char smem[];
    unsigned short* sE  = (unsigned short*)smem;
    float* sW  = (float*)(smem + 8192);
    float* sXA = (float*)(smem + 24576);
    float* sA  = (float*)(smem + 40960);
    float* sH  = (float*)(smem + 106496);
    float* sS  = (float*)(smem + 172032);
    float* sRed= (float*)(smem + 227328);

    const int g    = blockIdx.x;
    const int tid  = threadIdx.x;
    const int lane = tid & 31;
    const int warp = tid >> 5;

    float a2p = 0.f, linkp = 0.f, g2p = 0.f, entp = 0.f;

    // dst-sort scratch lives in sH region (free until phase 5)
    unsigned short* sEd  = (unsigned short*)sH;            // floats [0,2048)
    unsigned int*   dOff = (unsigned int*)(sH + 2048);     // 257
    unsigned int*   dPos = (unsigned int*)(sH + 2432);     // 256
    unsigned int*   wt   = (unsigned int*)(sRed + 192);    // 8 warp totals for scans

    // ============ phase 1: load x, edges; zero Acnt + dst counts ============
    {
        const float* xg = x + (size_t)g * NP * FIN;
        for (int i = tid; i < NP * FIN; i += 512) {
            int r = i / FIN, f = i - r * FIN;
            sXA[r * 8 + f] = xg[i];
        }
        for (int i = tid; i < 256; i += 512) sXA[i * 8 + 7] = 0.f;  // pad slot
        unsigned int* Ac = (unsigned int*)sA;
        for (int i = tid; i < 16384; i += 512) Ac[i] = 0u;
        if (tid < 256) dPos[tid] = 0u;
        const int* es = edge + (size_t)g * EPG;
        const int* ed = edge + (size_t)ETOT + (size_t)g * EPG;
        for (int e = tid; e < EPG; e += 512) {
            unsigned int s = ((unsigned int)es[e]) & 255u;
            unsigned int d = ((unsigned int)ed[e]) & 255u;
            sE[e] = (unsigned short)(s | (d << 8));
        }
    }
    __syncthreads();

    // ============ phase 2: A-count (sumA2) + dst counting ============
    {
        unsigned int* Ac = (unsigned int*)sA;
        for (int e = tid; e < EPG; e += 512) {
            unsigned int p = sE[e];
            unsigned int s = p & 255u, d = p >> 8;
            atomicAdd(&dPos[d], 1u);
            unsigned int cell = s * 256u + d;
            unsigned int w = cell >> 2, sh = (cell & 3u) * 8u;
            unsigned int old = atomicAdd(&Ac[w], 1u << sh);
            unsigned int c = (old >> sh) & 255u;
            a2p += (float)(2u * c + 1u);
        }
    }
    __syncthreads();
    // exclusive scan of dst counts
    unsigned int vcnt = 0, inc = 0;
    if (tid < 256) {
        vcnt = dPos[tid];
        inc = vcnt;
        #pragma unroll
        for (int o = 1; o < 32; o <<= 1) {
            unsigned int nv = __shfl_up_sync(0xffffffffu, inc, o);
            if (lane >= o) inc += nv;
        }
        if (lane == 31) wt[warp] = inc;
    }
    __syncthreads();
    if (tid < 256) {
        unsigned int base = 0;
        #pragma unroll
        for (int w = 0; w < 8; w++) base += (w < warp) ? wt[w] : 0u;
        dOff[tid] = base + inc - vcnt;
        if (tid == 255) dOff[256] = (unsigned int)EPG;
    }
    __syncthreads();
    if (tid < 256) dPos[tid] = dOff[tid];
    __syncthreads();
    for (int e = tid; e < EPG; e += 512) {
        unsigned int p = sE[e];
        unsigned int pos = atomicAdd(&dPos[p >> 8], 1u);
        sEd[pos] = (unsigned short)p;
    }
    __syncthreads();

    // ============ phase 3: agg gather; stage W1a ============
    {
        const ull ONE = pk2(1.f, 1.f);
        ull ag01 = 0ULL, ag23 = 0ULL, ag45 = 0ULL, ag67 = 0ULL;
        if (tid < 256) {
            unsigned int e0 = dOff[tid], e1 = dOff[tid + 1];
            for (unsigned int e = e0; e < e1; e++) {
                unsigned int s = ((unsigned int)sEd[e]) & 255u;
                const float* xs = &sXA[s * 8];
                ull v01 = *(const ull*)&xs[0];
                ull v23 = *(const ull*)&xs[2];
                ull v45 = *(const ull*)&xs[4];
                ull v67 = *(const ull*)&xs[6];
                fma2(ag01, v01, ONE);
                fma2(ag23, v23, ONE);
                fma2(ag45, v45, ONE);
                fma2(ag67, v67, ONE);
            }
        } else {
            int t2 = tid - 256;
            for (int i = t2; i < FIN * HD; i += 256) sW[i] = W1a[i];
            if (t2 < HD) sW[448 + t2] = b1a[t2];
        }
        __syncthreads();
        if (tid < 256) {
            float f0, f1;
            upk2(ag01, f0, f1); sXA[tid*8 + 0] += f0; sXA[tid*8 + 1] += f1;
            upk2(ag23, f0, f1); sXA[tid*8 + 2] += f0; sXA[tid*8 + 3] += f1;
            upk2(ag45, f0, f1); sXA[tid*8 + 4] += f0; sXA[tid*8 + 5] += f1;
            upk2(ag67, f0, f1); sXA[tid*8 + 6] += f0;   // slot 7 = pad
        }
    }
    __syncthreads();

    // ============ phase 4: t = relu(h0 @ W1a + b1a) -> sA [256][64] ============
    {
        int j = 2 * lane;
        float b0 = sW[448 + j], b1 = sW[448 + j + 1];
        for (int it = 0; it < 4; it++) {
            int r0 = warp * 4 + it * 64;
            float a0[4], a1[4];
            #pragma unroll
            for (int rr = 0; rr < 4; rr++) { a0[rr] = b0; a1[rr] = b1; }
            #pragma unroll
            for (int k = 0; k < FIN; k++) {
                float2 wv = *(const float2*)&sW[k * HD + j];
                #pragma unroll
                for (int rr = 0; rr < 4; rr++) {
                    float hv = sXA[(r0 + rr) * 8 + k];
                    a0[rr] += hv * wv.x; a1[rr] += hv * wv.y;
                }
            }
            #pragma unroll
            for (int rr = 0; rr < 4; rr++) {
                sA[(r0 + rr) * HD + j]     = fmaxf(a0[rr], 0.f);
                sA[(r0 + rr) * HD + j + 1] = fmaxf(a1[rr], 0.f);
            }
        }
    }
    __syncthreads();
    // stage W1b K-PAIR-INTERLEAVED: wI[(k>>1)*128 + j*2 + (k&1)]
    // load addresses (below) are lane-consecutive -> conflict-free (R9's bug fixed)
    for (int i = tid; i < HD * HD; i += 512) {
        int k = i >> 6, j = i & 63;
        sW[((k >> 1) << 7) + (j << 1) + (k & 1)] = W1b[i];
    }
    if (tid < HD) sRed[tid] = b1b[tid];
    __syncthreads();

    // ==== phase 5: h = t @ W1b + b1b -> sH (k-pair packed dot products) ====
    // lane = col pair (c0=2*lane, c0+1); warp = 16 rows in 2 passes of 8.
    // t pairs: broadcast LDS.64; W pairs for both cols: one LDS.128 (16B/lane,
    // lane-consecutive). NO splat MOVs; horizontal add at epilogue.
    {
        const int c0 = 2 * lane;
        float b0 = sRed[c0], b1 = sRed[c0 + 1];
        #pragma unroll
        for (int pass = 0; pass < 2; pass++) {
            const int r0 = warp * 16 + pass * 8;
            ull acc0[8] = {}, acc1[8] = {};
            for (int kp = 0; kp < 32; kp++) {
                ulonglong2 wv = *(const ulonglong2*)&sW[(kp << 7) + (c0 << 1)];
                #pragma unroll
                for (int i = 0; i < 8; i++) {
                    ull tp = *(const ull*)&sA[(r0 + i) * HD + 2 * kp];  // broadcast
                    fma2(acc0[i], tp, wv.x);
                    fma2(acc1[i], tp, wv.y);
                }
            }
            #pragma unroll
            for (int i = 0; i < 8; i++) {
                float x0, y0, x1, y1;
                upk2(acc0[i], x0, y0); upk2(acc1[i], x1, y1);
                *(ull*)&sH[(r0 + i) * HD + c0] = pk2(x0 + y0 + b0, x1 + y1 + b1);
            }
        }
    }
    __syncthreads();
    // stage Wp K-PAIR-INTERLEAVED: wI6[(k>>1)*100 + j*2 + (k&1)]
    for (int i = tid; i < HD * KC; i += 512) {
        int k = i / KC, j = i - k * KC;
        sW[(k >> 1) * 100 + (j << 1) + (k & 1)] = Wp[i];
    }
    if (tid < KC) sRed[tid] = bp[tid];
    __syncthreads();

    // ============ phase 6: S logits (k-pair packed) + softmax + entropy ============
    {
        const int c0 = 2 * lane;
        const bool act = (lane < 25);        // col pairs cover 0..49
        float b0 = act ? sRed[c0] : 0.f;
        float b1 = act ? sRed[c0 + 1] : 0.f;
        #pragma unroll
        for (int pass = 0; pass < 2; pass++) {
            const int r0 = warp * 16 + pass * 8;
            ull acc0[8] = {}, acc1[8] = {};
            for (int kp = 0; kp < 32; kp++) {
                // inactive lanes read in-bounds garbage (max idx 3299 < 4096)
                int ci = act ? (c0 << 1) : 0;
                ulonglong2 wv = *(const ulonglong2*)&sW[kp * 100 + ci];
                #pragma unroll
                for (int i = 0; i < 8; i++) {
                    ull hp = *(const ull*)&sH[(r0 + i) * HD + 2 * kp];  // broadcast
                    fma2(acc0[i], hp, wv.x);
                    fma2(acc1[i], hp, wv.y);
                }
            }
            if (act) {
                #pragma unroll
                for (int i = 0; i < 8; i++) {
                    float x0, y0, x1, y1;
                    upk2(acc0[i], x0, y0); upk2(acc1[i], x1, y1);
                    *(ull*)&sS[(r0 + i) * SK + c0] = pk2(x0 + y0 + b0, x1 + y1 + b1);
                }
            }
        }
    }
    __syncthreads();
    {   // softmax: 2 threads per row, 25 cols each; LOG-FREE entropy:
        // sum_k p_k log p_k = (sum_k e_k*(z_k - m))/Z - log Z
        int row = tid >> 1, half = tid & 1;
        float* rowp = &sS[row * SK + half * 25];
        float mx = rowp[0];
        #pragma unroll 5
        for (int k = 1; k < 25; k++) mx = fmaxf(mx, rowp[k]);
        mx = fmaxf(mx, __shfl_xor_sync(0xffffffffu, mx, 1));
        float sum = 0.f, sz = 0.f;
        #pragma unroll 5
        for (int k = 0; k < 25; k++) {
            float z = rowp[k] - mx;
            float e = __expf(z);
            rowp[k] = e;
            sum += e;
            sz = fmaf(e, z, sz);
        }
        sum += __shfl_xor_sync(0xffffffffu, sum, 1);
        float inv = 1.f / sum;
        #pragma unroll 5
        for (int k = 0; k < 25; k++) rowp[k] *= inv;
        entp += sz * inv;
        if (half == 0) entp -= __logf(sum);
    }
    __syncthreads();

    // ============ phase 7: counting-sort by src; AS = A@S (f32x2); linkAS ============
    unsigned short* sE2  = (unsigned short*)sXA;            // floats [0,2048)
    unsigned int*   sOff = (unsigned int*)(sXA + 2048);     // 257
    unsigned int*   sPos = (unsigned int*)(sXA + 2432);     // 256
    {
        if (tid < 256) sPos[tid] = 0u;
        __syncthreads();
        for (int e = tid; e < EPG; e += 512) atomicAdd(&sPos[sE[e] & 255u], 1u);
        __syncthreads();
        unsigned int vc = 0, ic = 0;
        if (tid < 256) {
            vc = sPos[tid]; ic = vc;
            #pragma unroll
            for (int o = 1; o < 32; o <<= 1) {
                unsigned int nv = __shfl_up_sync(0xffffffffu, ic, o);
                if (lane >= o) ic += nv;
            }
            if (lane == 31) wt[warp] = ic;
        }
        __syncthreads();
        if (tid < 256) {
            unsigned int base = 0;
            #pragma unroll
            for (int w = 0; w < 8; w++) base += (w < warp) ? wt[w] : 0u;
            sOff[tid] = base + ic - vc;
            if (tid == 255) sOff[256] = (unsigned int)EPG;
        }
        __syncthreads();
        if (tid < 256) sPos[tid] = sOff[tid];
        __syncthreads();
        for (int e = tid; e < EPG; e += 512) {
            unsigned int p = sE[e];
            unsigned int pos = atomicAdd(&sPos[p & 255u], 1u);
            sE2[pos] = (unsigned short)p;
        }
    }
    __syncthreads();
    {
        const ull ONE = pk2(1.f, 1.f);
        if (lane < 25) {
            int c2 = 2 * lane;                 // col pair (c2, c2+1)
            for (int m = 0; m < 16; m++) {
                int i = warp + m * 16;
                unsigned int e0 = sOff[i], e1 = sOff[i + 1];
                ull acc = 0ULL, lnk = 0ULL;
                ull si = *(const ull*)&sS[i * SK + c2];
                for (unsigned int e = e0; e < e1; e++) {
                    unsigned int d = ((unsigned int)sE2[e]) >> 8;
                    ull v = *(const ull*)&sS[d * SK + c2];
                    fma2(acc, v, ONE);
                    fma2(lnk, v, si);
                }
                *(ull*)&sA[i * SK + c2] = acc;
                float l0, l1; upk2(lnk, l0, l1);
                linkp += l0 + l1;
            }
        }
    }
    __syncthreads();

    // ==== phase 8 (concurrent): xp = S^T h | Ap & ||G||^2 | stage W2a ====
    float* xp = sXA;               // [50][64]
    float* Ap = sA + 256 * SK;     // [50][50] at float 13824
    if (tid < 208) {
        // group A: 13 k-blocks x 16 j-blocks; S scalars via pair loads
        int kb = tid >> 4, jb = tid & 15;
        int ks = kb * 4;
        int kn = (ks + 4 <= KC) ? 4 : (KC - ks);
        ull acc[4][2] = {};
        for (int n = 0; n < NP; n++) {
            ull h01 = *(const ull*)&sH[n * HD + jb * 4];
            ull h23 = *(const ull*)&sH[n * HD + jb * 4 + 2];
            ull s01 = *(const ull*)&sS[n * SK + ks];
            ull s23 = *(const ull*)&sS[n * SK + ks + 2];
            float sv0, sv1, sv2, sv3;
            upk2(s01, sv0, sv1); upk2(s23, sv2, sv3);
            float sv[4] = { sv0, sv1, sv2, sv3 };
            #pragma unroll
            for (int kk = 0; kk < 4; kk++) {
                ull sp = pk2(sv[kk], sv[kk]);
                fma2(acc[kk][0], sp, h01);
                fma2(acc[kk][1], sp, h23);
            }
        }
        for (int kk = 0; kk < kn; kk++) {
            float f0, f1, f2, f3;
            upk2(acc[kk][0], f0, f1); upk2(acc[kk][1], f2, f3);
            *(float4*)&xp[(ks + kk) * HD + jb * 4] = make_float4(f0, f1, f2, f3);
        }
    } else if (tid >= 224 && tid < 224 + 169) {
        // group B: Ap and sumG2, 13x13 4x4 blocks; S scalars via pair loads
        int u = tid - 224;
        int kb = u / 13, lb = u - kb * 13;
        int ks = kb * 4, ls = lb * 4;
        int kn = (ks + 4 <= KC) ? 4 : (KC - ks);
        int ln = (ls + 4 <= KC) ? 4 : (KC - ls);
        ull aA[4][2] = {}, aG[4][2] = {};
        for (int n = 0; n < NP; n++) {
            ull sl01 = *(const ull*)&sS[n * SK + ls];
            ull sl23 = *(const ull*)&sS[n * SK + ls + 2];
            ull al01 = *(const ull*)&sA[n * SK + ls];
            ull al23 = *(const ull*)&sA[n * SK + ls + 2];
            ull sk01 = *(const ull*)&sS[n * SK + ks];
            ull sk23 = *(const ull*)&sS[n * SK + ks + 2];
            float k0, k1, k2, k3;
            upk2(sk01, k0, k1); upk2(sk23, k2, k3);
            float kv[4] = { k0, k1, k2, k3 };
            #pragma unroll
            for (int a = 0; a < 4; a++) {
                ull sp = pk2(kv[a], kv[a]);
                fma2(aA[a][0], sp, al01); fma2(aA[a][1], sp, al23);
                fma2(aG[a][0], sp, sl01); fma2(aG[a][1], sp, sl23);
            }
        }
        for (int a = 0; a < kn; a++) {
            float fa0, fa1, fa2, fa3, ga0, ga1, ga2, ga3;
            upk2(aA[a][0], fa0, fa1); upk2(aA[a][1], fa2, fa3);
            upk2(aG[a][0], ga0, ga1); upk2(aG[a][1], ga2, ga3);
            float av[4] = { fa0, fa1, fa2, fa3 };
            float gv[4] = { ga0, ga1, ga2, ga3 };
            for (int b = 0; b < ln; b++) {
                Ap[(ks + a) * KC + ls + b] = av[b];
                g2p += gv[b] * gv[b];
            }
        }
    } else if (tid >= 448) {
        // group C: stage W2a + b2a (natural layout)
        int t2 = tid - 448;
        for (int i = t2; i < HD * HD; i += 64) sW[i] = W2a[i];
        if (t2 < HD) sRed[t2] = b2a[t2];
    }
    __syncthreads();

    // ============ phase 9: DenseGIN + mean pool + classifier ============
    // step1: h2a = xp + Ap @ xp -> sH
    for (int idx = tid; idx < KC * 16; idx += 512) {
        int k = idx >> 4, j = (idx & 15) * 4;
        ull a01 = *(const ull*)&xp[k * HD + j];
        ull a23 = *(const ull*)&xp[k * HD + j + 2];
        for (int l = 0; l < KC; l++) {
            float ap = Ap[k * KC + l];
            ull app = pk2(ap, ap);
            ull x01 = *(const ull*)&xp[l * HD + j];
            ull x23 = *(const ull*)&xp[l * HD + j + 2];
            fma2(a01, app, x01);
            fma2(a23, app, x23);
        }
        float f0, f1, f2, f3;
        upk2(a01, f0, f1); upk2(a23, f2, f3);
        *(float4*)&sH[k * HD + j] = make_float4(f0, f1, f2, f3);
    }
    __syncthreads();
    // step2: t2 = relu(h2a @ W2a + b2a) -> sA
    for (int idx = tid; idx < KC * 16; idx += 512) {
        int k = idx >> 4, j = (idx & 15) * 4;
        ull a01 = *(const ull*)&sRed[j];
        ull a23 = *(const ull*)&sRed[j + 2];
        for (int l = 0; l < HD; l++) {
            float hb = sH[k * HD + l];
            ull hp = pk2(hb, hb);
            ull w01 = *(const ull*)&sW[l * HD + j];
            ull w23 = *(const ull*)&sW[l * HD + j + 2];
            fma2(a01, hp, w01);
            fma2(a23, hp, w23);
        }
        float f0, f1, f2, f3;
        upk2(a01, f0, f1); upk2(a23, f2, f3);
        *(float4*)&sA[k * HD + j] = make_float4(fmaxf(f0, 0.f), fmaxf(f1, 0.f),
                                                fmaxf(f2, 0.f), fmaxf(f3, 0.f));
    }
    __syncthreads();
    for (int i = tid; i < HD * HD; i += 512) sW[i] = W2b[i];
    if (tid < HD) sRed[64 + tid] = b2b[tid];
    __syncthreads();
    // step3: m = mean_k t2  (mean before W2b: linear)
    if (tid < HD) {
        float s = 0.f;
        for (int k = 0; k < KC; k++) s += sA[k * HD + tid];
        sRed[128 + tid] = s * (1.f / (float)KC);
    }
    __syncthreads();
    // step4: logits = (m @ W2b + b2b) @ Wl + bl
    if (tid < HD) {
        float mb = sRed[64 + tid];
        for (int l = 0; l < HD; l++) mb += sRed[128 + l] * sW[l * HD + tid];
        float p0 = mb * Wl[tid * 2];
        float p1 = mb * Wl[tid * 2 + 1];
        #pragma unroll
        for (int o = 16; o > 0; o >>= 1) {
            p0 += __shfl_down_sync(0xffffffffu, p0, o);
            p1 += __shfl_down_sync(0xffffffffu, p1, o);
        }
        if (lane == 0) { sRed[280 + warp * 2] = p0; sRed[281 + warp * 2] = p1; }
    }
    __syncthreads();
    if (tid == 0) {
        float l0 = bl[0] + sRed[280] + sRed[282];
        float l1 = bl[1] + sRed[281] + sRed[283];
        float mx = fmaxf(l0, l1);
        float lse = mx + logf(expf(l0 - mx) + expf(l1 - mx));
        out[g * 2]     = l0 - lse;
        out[g * 2 + 1] = l1 - lse;
    }

    // ============ loss partials -> g_part ============
    {
        float v[4] = { a2p, linkp, g2p, entp };
        #pragma unroll
        for (int c = 0; c < 4; c++) {
            float t = v[c];
            #pragma unroll
            for (int o = 16; o > 0; o >>= 1) t += __shfl_down_sync(0xffffffffu, t, o);
            if (lane == 0) sRed[200 + warp * 4 + c] = t;
        }
        __syncthreads();
        if (tid == 0) {
            float s0 = 0, s1 = 0, s2 = 0, s3 = 0;
            for (int w = 0; w < 16; w++) {
                s0 += sRed[200 + w * 4];
                s1 += sRed[200 + w * 4 + 1];
                s2 += sRed[200 + w * 4 + 2];
                s3 += sRed[200 + w * 4 + 3];
            }
            g_part[g * 4]     = s0;
            g_part[g * 4 + 1] = s1;
            g_part[g * 4 + 2] = s2;
            g_part[g * 4 + 3] = s3;
        }
    }

    // ============ last-CTA global reduction ============
    if (tid == 0) {
        __threadfence();
        unsigned int old = atomicAdd(&g_ctr, 1u);
        sRed[287] = (old == NB - 1) ? 1.f : 0.f;
    }
    __syncthreads();
    if (sRed[287] != 0.f) {
        float s0 = 0, s1 = 0, s2 = 0, s3 = 0;
        for (int i = tid; i < NB; i += 512) {
            const float* p = &g_part[i * 4];
            s0 += p[0]; s1 += p[1]; s2 += p[2]; s3 += p[3];
        }
        #pragma unroll
        for (int o = 16; o > 0; o >>= 1) {
            s0 += __shfl_down_sync(0xffffffffu, s0, o);
            s1 += __shfl_down_sync(0xffffffffu, s1, o);
            s2 += __shfl_down_sync(0xffffffffu, s2, o);
            s3 += __shfl_down_sync(0xffffffffu, s3, o);
        }
        if (lane == 0) {
            sRed[warp * 4]     = s0;
            sRed[warp * 4 + 1] = s1;
            sRed[warp * 4 + 2] = s2;
            sRed[warp * 4 + 3] = s3;
        }
        __syncthreads();
        if (tid == 0) {
            float t0 = 0, t1 = 0, t2 = 0, t3 = 0;
            for (int w = 0; w < 16; w++) {
                t0 += sRed[w * 4];
                t1 += sRed[w * 4 + 1];
                t2 += sRed[w * 4 + 2];
                t3 += sRed[w * 4 + 3];
            }
            float q = t0 - 2.f * t1 + t2;
            q = fmaxf(q, 0.f);
            float link = sqrtf(q) / ((float)NB * (float)NP * (float)NP);
            float ent = -t3 / ((float)NB * (float)NP);
            if (out_size > NB * 2) out[NB * 2] = link + ent;
            g_ctr = 0;   // reset for next replay
        }
    }
}

extern "C" void kernel_launch(void* const* d_in, const int* in_sizes, int n_in,
                              void* d_out, int out_size)
{
    cudaFuncSetAttribute(net_main, cudaFuncAttributeMaxDynamicSharedMemorySize, SMEM_BYTES);

    const float* x   = (const float*)d_in[0];
    const float* W1a = (const float*)d_in[1];
    const float* b1a = (const float*)d_in[2];
    const float* W1b = (const float*)d_in[3];
    const float* b1b = (const float*)d_in[4];
    const float* Wp  = (const float*)d_in[5];
    const float* bp  = (const float*)d_in[6];
    const float* W2a = (const float*)d_in[7];
    const float* b2a = (const float*)d_in[8];
    const float* W2b = (const float*)d_in[9];
    const float* b2b = (const float*)d_in[10];
    const float* Wl  = (const float*)d_in[11];
    const float* bl  = (const float*)d_in[12];
    const int* edge  = (const int*)d_in[13];
    float* out = (float*)d_out;

    net_main<<<NB, 512, SMEM_BYTES>>>(x, W1a, b1a, W1b, b1b, Wp, bp,
                                      W2a, b2a, W2b, b2b, Wl, bl, edge,
                                      out, out_size);
}

// round 16
// speedup vs baseline: 1.0559x; 1.0559x over previous
#include <cuda_runtime.h>
#include <cuda_bf16.h>
#include <math.h>

// Problem constants
#define NB    1024
#define NP    256
#define EPG   4096
#define ETOT  (NB*EPG)
#define FIN   7
#define HD    64
#define KC    50
#define SK    54          // EVEN stride -> 8B-aligned col pairs for LDS.64/f32x2

// dynamic smem layout (bytes)
//  0      : sE   u16[4096]            8192
//  8192   : sW   float[4096]          16384
//  24576  : sXA  float[4096]          16384   (x/h0; sort scratch; xp)
//  40960  : sA   float[16384]         65536   (Acnt u32 / t / AS[256*54]+Ap / t2)
//  106496 : sH   float[16384]         65536   (dst-sort scratch; h; h2a)
//  172032 : sS   float[256*54]        55296
//  227328 : sRed float[288]           1152
#define SMEM_BYTES 228480

__device__ float g_part[NB * 4];
__device__ unsigned int g_ctr = 0;

typedef unsigned long long ull;

// ---- packed f32x2 helpers (Blackwell FFMA2) ----
__device__ __forceinline__ ull pk2(float a, float b) {
    ull r;
    asm("mov.b64 %0, {%1,%2};" : "=l"(r) : "f"(a), "f"(b));
    return r;
}
__device__ __forceinline__ void upk2(ull v, float& a, float& b) {
    asm("mov.b64 {%0,%1}, %2;" : "=f"(a), "=f"(b) : "l"(v));
}
__device__ __forceinline__ void fma2(ull& d, ull a, ull b) {
    asm("fma.rn.f32x2 %0, %1, %2, %3;" : "=l"(d) : "l"(a), "l"(b), "l"(d));
}

__global__ __launch_bounds__(512, 1) void net_main(
    const float* __restrict__ x,
    const float* __restrict__ W1a, const float* __restrict__ b1a,
    const float* __restrict__ W1b, const float* __restrict__ b1b,
    const float* __restrict__ Wp,  const float* __restrict__ bp,
    const float* __restrict__ W2a, const float* __restrict__ b2a,
    const float* __restrict__ W2b, const float* __restrict__ b2b,
    const float* __restrict__ Wl,  const float* __restrict__ bl,
    const int* __restrict__ edge,   // [2][ETOT] int32
    float* __restrict__ out, int out_size)
{
    extern __shared__ char smem[];
    unsigned short* sE  = (unsigned short*)smem;
    float* sW  = (float*)(smem + 8192);
    float* sXA = (float*)(smem + 24576);
    float* sA  = (float*)(smem + 40960);
    float* sH  = (float*)(smem + 106496);
    float* sS  = (float*)(smem + 172032);
    float* sRed= (float*)(smem + 227328);

    const int g    = blockIdx.x;
    const int tid  = threadIdx.x;
    const int lane = tid & 31;
    const int warp = tid >> 5;

    float a2p = 0.f, linkp = 0.f, g2p = 0.f, entp = 0.f;

    // dst-sort scratch lives in sH region (free until phase 5)
    unsigned short* sEd  = (unsigned short*)sH;            // floats [0,2048)
    unsigned int*   dOff = (unsigned int*)(sH + 2048);     // 257
    unsigned int*   dPos = (unsigned int*)(sH + 2432);     // 256
    unsigned int*   wt   = (unsigned int*)(sRed + 192);    // 8 warp totals for scans

    // ============ phase 1: load x, edges; zero Acnt + dst counts ============
    {
        const float* xg = x + (size_t)g * NP * FIN;
        for (int i = tid; i < NP * FIN; i += 512) {
            int r = i / FIN, f = i - r * FIN;
            sXA[r * 8 + f] = xg[i];
        }
        for (int i = tid; i < 256; i += 512) sXA[i * 8 + 7] = 0.f;  // pad slot
        unsigned int* Ac = (unsigned int*)sA;
        for (int i = tid; i < 16384; i += 512) Ac[i] = 0u;
        if (tid < 256) dPos[tid] = 0u;
        const int* es = edge + (size_t)g * EPG;
        const int* ed = edge + (size_t)ETOT + (size_t)g * EPG;
        for (int e = tid; e < EPG; e += 512) {
            unsigned int s = ((unsigned int)es[e]) & 255u;
            unsigned int d = ((unsigned int)ed[e]) & 255u;
            sE[e] = (unsigned short)(s | (d << 8));
        }
    }
    __syncthreads();

    // ============ phase 2: A-count (sumA2) + dst counting ============
    {
        unsigned int* Ac = (unsigned int*)sA;
        for (int e = tid; e < EPG; e += 512) {
            unsigned int p = sE[e];
            unsigned int s = p & 255u, d = p >> 8;
            atomicAdd(&dPos[d], 1u);
            unsigned int cell = s * 256u + d;
            unsigned int w = cell >> 2, sh = (cell & 3u) * 8u;
            unsigned int old = atomicAdd(&Ac[w], 1u << sh);
            unsigned int c = (old >> sh) & 255u;
            a2p += (float)(2u * c + 1u);
        }
    }
    __syncthreads();
    // exclusive scan of dst counts
    unsigned int vcnt = 0, inc = 0;
    if (tid < 256) {
        vcnt = dPos[tid];
        inc = vcnt;
        #pragma unroll
        for (int o = 1; o < 32; o <<= 1) {
            unsigned int nv = __shfl_up_sync(0xffffffffu, inc, o);
            if (lane >= o) inc += nv;
        }
        if (lane == 31) wt[warp] = inc;
    }
    __syncthreads();
    if (tid < 256) {
        unsigned int base = 0;
        #pragma unroll
        for (int w = 0; w < 8; w++) base += (w < warp) ? wt[w] : 0u;
        dOff[tid] = base + inc - vcnt;
        if (tid == 255) dOff[256] = (unsigned int)EPG;
    }
    __syncthreads();
    if (tid < 256) dPos[tid] = dOff[tid];
    __syncthreads();
    for (int e = tid; e < EPG; e += 512) {
        unsigned int p = sE[e];
        unsigned int pos = atomicAdd(&dPos[p >> 8], 1u);
        sEd[pos] = (unsigned short)p;
    }
    __syncthreads();

    // ============ phase 3: agg gather; stage W1a ============
    {
        const ull ONE = pk2(1.f, 1.f);
        ull ag01 = 0ULL, ag23 = 0ULL, ag45 = 0ULL, ag67 = 0ULL;
        if (tid < 256) {
            unsigned int e0 = dOff[tid], e1 = dOff[tid + 1];
            for (unsigned int e = e0; e < e1; e++) {
                unsigned int s = ((unsigned int)sEd[e]) & 255u;
                const float* xs = &sXA[s * 8];
                ull v01 = *(const ull*)&xs[0];
                ull v23 = *(const ull*)&xs[2];
                ull v45 = *(const ull*)&xs[4];
                ull v67 = *(const ull*)&xs[6];
                fma2(ag01, v01, ONE);
                fma2(ag23, v23, ONE);
                fma2(ag45, v45, ONE);
                fma2(ag67, v67, ONE);
            }
        } else {
            int t2 = tid - 256;
            for (int i = t2; i < FIN * HD; i += 256) sW[i] = W1a[i];
            if (t2 < HD) sW[448 + t2] = b1a[t2];
        }
        __syncthreads();
        if (tid < 256) {
            float f0, f1;
            upk2(ag01, f0, f1); sXA[tid*8 + 0] += f0; sXA[tid*8 + 1] += f1;
            upk2(ag23, f0, f1); sXA[tid*8 + 2] += f0; sXA[tid*8 + 3] += f1;
            upk2(ag45, f0, f1); sXA[tid*8 + 4] += f0; sXA[tid*8 + 5] += f1;
            upk2(ag67, f0, f1); sXA[tid*8 + 6] += f0;   // slot 7 = pad
        }
    }
    __syncthreads();

    // ============ phase 4: t = relu(h0 @ W1a + b1a) -> sA [256][64] ============
    {
        int j = 2 * lane;
        float b0 = sW[448 + j], b1 = sW[448 + j + 1];
        for (int it = 0; it < 4; it++) {
            int r0 = warp * 4 + it * 64;
            float a0[4], a1[4];
            #pragma unroll
            for (int rr = 0; rr < 4; rr++) { a0[rr] = b0; a1[rr] = b1; }
            #pragma unroll
            for (int k = 0; k < FIN; k++) {
                float2 wv = *(const float2*)&sW[k * HD + j];
                #pragma unroll
                for (int rr = 0; rr < 4; rr++) {
                    float hv = sXA[(r0 + rr) * 8 + k];
                    a0[rr] += hv * wv.x; a1[rr] += hv * wv.y;
                }
            }
            #pragma unroll
            for (int rr = 0; rr < 4; rr++) {
                sA[(r0 + rr) * HD + j]     = fmaxf(a0[rr], 0.f);
                sA[(r0 + rr) * HD + j + 1] = fmaxf(a1[rr], 0.f);
            }
        }
    }
    __syncthreads();
    for (int i = tid; i < HD * HD; i += 512) sW[i] = W1b[i];   // natural [64][64]
    if (tid < HD) sRed[tid] = b1b[tid];
    __syncthreads();

    // ==== phase 5: h = t @ W1b + b1b -> sH (broadcast A, conflict-free W) ====
    {
        const int j = 2 * lane;
        const int r0 = warp * 16;
        ull bj = *(const ull*)&sRed[j];
        ull acc[16];
        #pragma unroll
        for (int i = 0; i < 16; i++) acc[i] = bj;
        for (int kp = 0; kp < 32; kp++) {
            ull w0 = *(const ull*)&sW[(2 * kp) * HD + j];
            ull w1 = *(const ull*)&sW[(2 * kp + 1) * HD + j];
            #pragma unroll
            for (int i = 0; i < 16; i++) {
                ull tp = *(const ull*)&sA[(r0 + i) * HD + 2 * kp];  // broadcast
                float ta, tb; upk2(tp, ta, tb);
                fma2(acc[i], pk2(ta, ta), w0);
                fma2(acc[i], pk2(tb, tb), w1);
            }
        }
        #pragma unroll
        for (int i = 0; i < 16; i++)
            *(ull*)&sH[(r0 + i) * HD + j] = acc[i];
    }
    __syncthreads();
    for (int i = tid; i < HD * KC; i += 512) sW[i] = Wp[i];    // natural [64][50]
    if (tid < KC) sRed[tid] = bp[tid];
    __syncthreads();

    // ============ phase 6: S logits + softmax + entropy ============
    {
        const int j = 2 * lane;
        const int r0 = warp * 16;
        const bool act = (lane < 25);
        ull bj = act ? *(const ull*)&sRed[j] : 0ULL;
        ull acc[16];
        #pragma unroll
        for (int i = 0; i < 16; i++) acc[i] = bj;
        for (int kp = 0; kp < 32; kp++) {
            ull w0 = *(const ull*)&sW[(2 * kp) * KC + j];
            ull w1 = *(const ull*)&sW[(2 * kp + 1) * KC + j];
            #pragma unroll
            for (int i = 0; i < 16; i++) {
                ull hp = *(const ull*)&sH[(r0 + i) * HD + 2 * kp];  // broadcast
                float ha, hb; upk2(hp, ha, hb);
                fma2(acc[i], pk2(ha, ha), w0);
                fma2(acc[i], pk2(hb, hb), w1);
            }
        }
        if (act) {
            #pragma unroll
            for (int i = 0; i < 16; i++)
                *(ull*)&sS[(r0 + i) * SK + j] = acc[i];
        }
    }
    __syncthreads();
    {   // softmax: 2 threads per row, 25 cols each; LOG-FREE entropy:
        // sum_k p_k log p_k = (sum_k e_k*(z_k - m))/Z - log Z
        int row = tid >> 1, half = tid & 1;
        float* rowp = &sS[row * SK + half * 25];
        float mx = rowp[0];
        #pragma unroll 5
        for (int k = 1; k < 25; k++) mx = fmaxf(mx, rowp[k]);
        mx = fmaxf(mx, __shfl_xor_sync(0xffffffffu, mx, 1));
        float sum = 0.f, sz = 0.f;
        #pragma unroll 5
        for (int k = 0; k < 25; k++) {
            float z = rowp[k] - mx;
            float e = __expf(z);
            rowp[k] = e;
            sum += e;
            sz = fmaf(e, z, sz);
        }
        sum += __shfl_xor_sync(0xffffffffu, sum, 1);
        float inv = 1.f / sum;
        #pragma unroll 5
        for (int k = 0; k < 25; k++) rowp[k] *= inv;
        entp += sz * inv;
        if (half == 0) entp -= __logf(sum);
    }
    __syncthreads();

    // ============ phase 7: counting-sort by src; AS = A@S (f32x2); linkAS ============
    unsigned short* sE2  = (unsigned short*)sXA;            // floats [0,2048)
    unsigned int*   sOff = (unsigned int*)(sXA + 2048);     // 257
    unsigned int*   sPos = (unsigned int*)(sXA + 2432);     // 256
    {
        if (tid < 256) sPos[tid] = 0u;
        __syncthreads();
        for (int e = tid; e < EPG; e += 512) atomicAdd(&sPos[sE[e] & 255u], 1u);
        __syncthreads();
        unsigned int vc = 0, ic = 0;
        if (tid < 256) {
            vc = sPos[tid]; ic = vc;
            #pragma unroll
            for (int o = 1; o < 32; o <<= 1) {
                unsigned int nv = __shfl_up_sync(0xffffffffu, ic, o);
                if (lane >= o) ic += nv;
            }
            if (lane == 31) wt[warp] = ic;
        }
        __syncthreads();
        if (tid < 256) {
            unsigned int base = 0;
            #pragma unroll
            for (int w = 0; w < 8; w++) base += (w < warp) ? wt[w] : 0u;
            sOff[tid] = base + ic - vc;
            if (tid == 255) sOff[256] = (unsigned int)EPG;
        }
        __syncthreads();
        if (tid < 256) sPos[tid] = sOff[tid];
        __syncthreads();
        for (int e = tid; e < EPG; e += 512) {
            unsigned int p = sE[e];
            unsigned int pos = atomicAdd(&sPos[p & 255u], 1u);
            sE2[pos] = (unsigned short)p;
        }
    }
    __syncthreads();
    {
        const ull ONE = pk2(1.f, 1.f);
        if (lane < 25) {
            int c2 = 2 * lane;                 // col pair (c2, c2+1)
            for (int m = 0; m < 16; m++) {
                int i = warp + m * 16;
                unsigned int e0 = sOff[i], e1 = sOff[i + 1];
                ull acc = 0ULL, lnk = 0ULL;
                ull si = *(const ull*)&sS[i * SK + c2];
                for (unsigned int e = e0; e < e1; e++) {
                    unsigned int d = ((unsigned int)sE2[e]) >> 8;
                    ull v = *(const ull*)&sS[d * SK + c2];
                    fma2(acc, v, ONE);
                    fma2(lnk, v, si);
                }
                *(ull*)&sA[i * SK + c2] = acc;
                float l0, l1; upk2(lnk, l0, l1);
                linkp += l0 + l1;
            }
        }
    }
    __syncthreads();

    // ==== phase 8 (concurrent): xp = S^T h (8k x 4j tiles) | Ap & ||G||^2 | stage W2a ====
    float* xp = sXA;               // [50][64]
    float* Ap = sA + 256 * SK;     // [50][50] at float 13824
    if (tid < 112) {
        // group A: 7 kb-groups (8 k each) x 16 j-blocks — halves h-row re-reads
        int kb = tid >> 4, jb = tid & 15;   // kb 0..6
        int ks = kb * 8;
        int kn = (ks + 8 <= KC) ? 8 : (KC - ks);   // 8, or 2 for kb=6
        ull acc[8][2] = {};
        for (int n = 0; n < NP; n++) {
            ull h01 = *(const ull*)&sH[n * HD + jb * 4];
            ull h23 = *(const ull*)&sH[n * HD + jb * 4 + 2];
            const float* srow = &sS[n * SK + ks];
            // kb=6 reads into row pad / next row; values land only in
            // discarded accumulators (kk >= kn). All reads stay inside smem.
            ull s01 = *(const ull*)&srow[0];
            ull s23 = *(const ull*)&srow[2];
            ull s45 = *(const ull*)&srow[4];
            ull s67 = *(const ull*)&srow[6];
            float sv[8];
            upk2(s01, sv[0], sv[1]); upk2(s23, sv[2], sv[3]);
            upk2(s45, sv[4], sv[5]); upk2(s67, sv[6], sv[7]);
            #pragma unroll
            for (int kk = 0; kk < 8; kk++) {
                ull sp = pk2(sv[kk], sv[kk]);
                fma2(acc[kk][0], sp, h01);
                fma2(acc[kk][1], sp, h23);
            }
        }
        for (int kk = 0; kk < kn; kk++) {
            float f0, f1, f2, f3;
            upk2(acc[kk][0], f0, f1); upk2(acc[kk][1], f2, f3);
            *(float4*)&xp[(ks + kk) * HD + jb * 4] = make_float4(f0, f1, f2, f3);
        }
    } else if (tid >= 224 && tid < 224 + 169) {
        // group B: Ap and sumG2, 13x13 4x4 blocks; S scalars via pair loads
        int u = tid - 224;
        int kb = u / 13, lb = u - kb * 13;
        int ks = kb * 4, ls = lb * 4;
        int kn = (ks + 4 <= KC) ? 4 : (KC - ks);
        int ln = (ls + 4 <= KC) ? 4 : (KC - ls);
        ull aA[4][2] = {}, aG[4][2] = {};
        for (int n = 0; n < NP; n++) {
            ull sl01 = *(const ull*)&sS[n * SK + ls];
            ull sl23 = *(const ull*)&sS[n * SK + ls + 2];
            ull al01 = *(const ull*)&sA[n * SK + ls];
            ull al23 = *(const ull*)&sA[n * SK + ls + 2];
            ull sk01 = *(const ull*)&sS[n * SK + ks];
            ull sk23 = *(const ull*)&sS[n * SK + ks + 2];
            float k0, k1, k2, k3;
            upk2(sk01, k0, k1); upk2(sk23, k2, k3);
            float kv[4] = { k0, k1, k2, k3 };
            #pragma unroll
            for (int a = 0; a < 4; a++) {
                ull sp = pk2(kv[a], kv[a]);
                fma2(aA[a][0], sp, al01); fma2(aA[a][1], sp, al23);
                fma2(aG[a][0], sp, sl01); fma2(aG[a][1], sp, sl23);
            }
        }
        for (int a = 0; a < kn; a++) {
            float fa0, fa1, fa2, fa3, ga0, ga1, ga2, ga3;
            upk2(aA[a][0], fa0, fa1); upk2(aA[a][1], fa2, fa3);
            upk2(aG[a][0], ga0, ga1); upk2(aG[a][1], ga2, ga3);
            float av[4] = { fa0, fa1, fa2, fa3 };
            float gv[4] = { ga0, ga1, ga2, ga3 };
            for (int b = 0; b < ln; b++) {
                Ap[(ks + a) * KC + ls + b] = av[b];
                g2p += gv[b] * gv[b];
            }
        }
    } else if (tid >= 448) {
        // group C: stage W2a + b2a (natural layout)
        int t2 = tid - 448;
        for (int i = t2; i < HD * HD; i += 64) sW[i] = W2a[i];
        if (t2 < HD) sRed[t2] = b2a[t2];
    }
    __syncthreads();

    // ============ phase 9: DenseGIN + mean pool + classifier ============
    // step1: h2a = xp + Ap @ xp -> sH
    for (int idx = tid; idx < KC * 16; idx += 512) {
        int k = idx >> 4, j = (idx & 15) * 4;
        ull a01 = *(const ull*)&xp[k * HD + j];
        ull a23 = *(const ull*)&xp[k * HD + j + 2];
        for (int l = 0; l < KC; l++) {
            float ap = Ap[k * KC + l];
            ull app = pk2(ap, ap);
            ull x01 = *(const ull*)&xp[l * HD + j];
            ull x23 = *(const ull*)&xp[l * HD + j + 2];
            fma2(a01, app, x01);
            fma2(a23, app, x23);
        }
        float f0, f1, f2, f3;
        upk2(a01, f0, f1); upk2(a23, f2, f3);
        *(float4*)&sH[k * HD + j] = make_float4(f0, f1, f2, f3);
    }
    __syncthreads();
    // step2: t2 = relu(h2a @ W2a + b2a) -> sA
    for (int idx = tid; idx < KC * 16; idx += 512) {
        int k = idx >> 4, j = (idx & 15) * 4;
        ull a01 = *(const ull*)&sRed[j];
        ull a23 = *(const ull*)&sRed[j + 2];
        for (int l = 0; l < HD; l++) {
            float hb = sH[k * HD + l];
            ull hp = pk2(hb, hb);
            ull w01 = *(const ull*)&sW[l * HD + j];
            ull w23 = *(const ull*)&sW[l * HD + j + 2];
            fma2(a01, hp, w01);
            fma2(a23, hp, w23);
        }
        float f0, f1, f2, f3;
        upk2(a01, f0, f1); upk2(a23, f2, f3);
        *(float4*)&sA[k * HD + j] = make_float4(fmaxf(f0, 0.f), fmaxf(f1, 0.f),
                                                fmaxf(f2, 0.f), fmaxf(f3, 0.f));
    }
    __syncthreads();
    for (int i = tid; i < HD * HD; i += 512) sW[i] = W2b[i];
    if (tid < HD) sRed[64 + tid] = b2b[tid];
    __syncthreads();
    // step3: m = mean_k t2  (mean before W2b: linear)
    if (tid < HD) {
        float s = 0.f;
        for (int k = 0; k < KC; k++) s += sA[k * HD + tid];
        sRed[128 + tid] = s * (1.f / (float)KC);
    }
    __syncthreads();
    // step4: logits = (m @ W2b + b2b) @ Wl + bl
    if (tid < HD) {
        float mb = sRed[64 + tid];
        for (int l = 0; l < HD; l++) mb += sRed[128 + l] * sW[l * HD + tid];
        float p0 = mb * Wl[tid * 2];
        float p1 = mb * Wl[tid * 2 + 1];
        #pragma unroll
        for (int o = 16; o > 0; o >>= 1) {
            p0 += __shfl_down_sync(0xffffffffu, p0, o);
            p1 += __shfl_down_sync(0xffffffffu, p1, o);
        }
        if (lane == 0) { sRed[280 + warp * 2] = p0; sRed[281 + warp * 2] = p1; }
    }
    __syncthreads();
    if (tid == 0) {
        float l0 = bl[0] + sRed[280] + sRed[282];
        float l1 = bl[1] + sRed[281] + sRed[283];
        float mx = fmaxf(l0, l1);
        float lse = mx + logf(expf(l0 - mx) + expf(l1 - mx));
        out[g * 2]     = l0 - lse;
        out[g * 2 + 1] = l1 - lse;
    }

    // ============ loss partials -> g_part ============
    {
        float v[4] = { a2p, linkp, g2p, entp };
        #pragma unroll
        for (int c = 0; c < 4; c++) {
            float t = v[c];
            #pragma unroll
            for (int o = 16; o > 0; o >>= 1) t += __shfl_down_sync(0xffffffffu, t, o);
            if (lane == 0) sRed[200 + warp * 4 + c] = t;
        }
        __syncthreads();
        if (tid == 0) {
            float s0 = 0, s1 = 0, s2 = 0, s3 = 0;
            for (int w = 0; w < 16; w++) {
                s0 += sRed[200 + w * 4];
                s1 += sRed[200 + w * 4 + 1];
                s2 += sRed[200 + w * 4 + 2];
                s3 += sRed[200 + w * 4 + 3];
            }
            g_part[g * 4]     = s0;
            g_part[g * 4 + 1] = s1;
            g_part[g * 4 + 2] = s2;
            g_part[g * 4 + 3] = s3;
        }
    }

    // ============ last-CTA global reduction ============
    if (tid == 0) {
        __threadfence();
        unsigned int old = atomicAdd(&g_ctr, 1u);
        sRed[287] = (old == NB - 1) ? 1.f : 0.f;
    }
    __syncthreads();
    if (sRed[287] != 0.f) {
        float s0 = 0, s1 = 0, s2 = 0, s3 = 0;
        for (int i = tid; i < NB; i += 512) {
            const float* p = &g_part[i * 4];
            s0 += p[0]; s1 += p[1]; s2 += p[2]; s3 += p[3];
        }
        #pragma unroll
        for (int o = 16; o > 0; o >>= 1) {
            s0 += __shfl_down_sync(0xffffffffu, s0, o);
            s1 += __shfl_down_sync(0xffffffffu, s1, o);
            s2 += __shfl_down_sync(0xffffffffu, s2, o);
            s3 += __shfl_down_sync(0xffffffffu, s3, o);
        }
        if (lane == 0) {
            sRed[warp * 4]     = s0;
            sRed[warp * 4 + 1] = s1;
            sRed[warp * 4 + 2] = s2;
            sRed[warp * 4 + 3] = s3;
        }
        __syncthreads();
        if (tid == 0) {
            float t0 = 0, t1 = 0, t2 = 0, t3 = 0;
            for (int w = 0; w < 16; w++) {
                t0 += sRed[w * 4];
                t1 += sRed[w * 4 + 1];
                t2 += sRed[w * 4 + 2];
                t3 += sRed[w * 4 + 3];
            }
            float q = t0 - 2.f * t1 + t2;
            q = fmaxf(q, 0.f);
            float link = sqrtf(q) / ((float)NB * (float)NP * (float)NP);
            float ent = -t3 / ((float)NB * (float)NP);
            if (out_size > NB * 2) out[NB * 2] = link + ent;
            g_ctr = 0;   // reset for next replay
        }
    }
}

extern "C" void kernel_launch(void* const* d_in, const int* in_sizes, int n_in,
                              void* d_out, int out_size)
{
    cudaFuncSetAttribute(net_main, cudaFuncAttributeMaxDynamicSharedMemorySize, SMEM_BYTES);

    const float* x   = (const float*)d_in[0];
    const float* W1a = (const float*)d_in[1];
    const float* b1a = (const float*)d_in[2];
    const float* W1b = (const float*)d_in[3];
    const float* b1b = (const float*)d_in[4];
    const float* Wp  = (const float*)d_in[5];
    const float* bp  = (const float*)d_in[6];
    const float* W2a = (const float*)d_in[7];
    const float* b2a = (const float*)d_in[8];
    const float* W2b = (const float*)d_in[9];
    const float* b2b = (const float*)d_in[10];
    const float* Wl  = (const float*)d_in[11];
    const float* bl  = (const float*)d_in[12];
    const int* edge  = (const int*)d_in[13];
    float* out = (float*)d_out;

    net_main<<<NB, 512, SMEM_BYTES>>>(x, W1a, b1a, W1b, b1b, Wp, bp,
                                      W2a, b2a, W2b, b2b, Wl, bl, edge,
                                      out, out_size);
}